// round 3
// baseline (speedup 1.0000x reference)
#include <cuda_runtime.h>
#include <cuda_bf16.h>
#include <cstdint>

// ---------------------------------------------------------------------------
// Problem constants
// ---------------------------------------------------------------------------
#define IN_F   4096
#define OUT_F  4096
#define NBLKS  128      // IN_F / 32
#define MROWS  16384    // 4 * 4096 tokens

// Scratch (allocation-free rule: __device__ globals)
__device__ float g_Q[NBLKS * 32 * 32];            // 512 KB
__device__ float g_W2[(size_t)OUT_F * IN_F];      // 64 MB rotated+dequantized W (tf32 RNA-rounded)

// ---------------------------------------------------------------------------
// Helpers
// ---------------------------------------------------------------------------
__device__ __forceinline__ void cp16(void* s, const void* g) {
    uint32_t sa;
    asm("{ .reg .u64 t; cvta.to.shared.u64 t, %1; cvt.u32.u64 %0, t; }" : "=r"(sa) : "l"(s));
    asm volatile("cp.async.cg.shared.global [%0], [%1], 16;" :: "r"(sa), "l"(g));
}
#define CP_COMMIT() asm volatile("cp.async.commit_group;" ::: "memory")
#define CP_WAIT(n)  asm volatile("cp.async.wait_group %0;" :: "n"(n) : "memory")

__device__ __forceinline__ uint32_t cvt_rna_tf32(float f) {
    uint32_t t;
    asm("cvt.rna.tf32.f32 %0, %1;" : "=r"(t) : "f"(f));
    return t;
}

__device__ __forceinline__ void mma_tf32_16x8x8(float c[4], const uint32_t a[4], const uint32_t b[2]) {
    asm volatile(
        "mma.sync.aligned.m16n8k8.row.col.f32.tf32.tf32.f32 "
        "{%0,%1,%2,%3}, {%4,%5,%6,%7}, {%8,%9}, {%0,%1,%2,%3};"
        : "+f"(c[0]), "+f"(c[1]), "+f"(c[2]), "+f"(c[3])
        : "r"(a[0]), "r"(a[1]), "r"(a[2]), "r"(a[3]), "r"(b[0]), "r"(b[1]));
}

// ---------------------------------------------------------------------------
// Kernel 1: Cayley  Q = (I-S)^{-1}(I+S)   (Gauss-Jordan, diag-dominant, no pivot)
// ---------------------------------------------------------------------------
__global__ void cayley_kernel(const float* __restrict__ oft_r) {
    __shared__ float A[32][33];
    __shared__ float Bm[32][33];
    int n = blockIdx.x;
    int j = threadIdx.x, i = threadIdx.y;
    const float* R = oft_r + n * 1024;
    float s  = 0.5f * (R[i * 32 + j] - R[j * 32 + i]);
    float id = (i == j) ? 1.0f : 0.0f;
    A[i][j]  = id - s;
    Bm[i][j] = id + s;
    __syncthreads();
    for (int k = 0; k < 32; k++) {
        float fac = A[i][k] / A[k][k];
        __syncthreads();
        if (i != k) {
            A[i][j]  = fmaf(-fac, A[k][j],  A[i][j]);
            Bm[i][j] = fmaf(-fac, Bm[k][j], Bm[i][j]);
        }
        __syncthreads();
    }
    g_Q[n * 1024 + i * 32 + j] = Bm[i][j] / A[i][i];
}

// ---------------------------------------------------------------------------
// Kernel 2: dequant + fold rotation into W:
//   W2[o, n*32+j] = scales[o] * sum_k Q[n][j][k] * CB[codes[o, 4n + k/8]][k%8]
// One warp per (o, n). RNA-round to tf32 (B operand exact in MMA).
// ---------------------------------------------------------------------------
__global__ __launch_bounds__(256) void dequant_kernel(
    const int* __restrict__ codes, const float* __restrict__ codebooks,
    const float* __restrict__ scales)
{
    __shared__ float Qs[32][33];
    int n = blockIdx.x;                // 0..127
    int obase = blockIdx.y * 8;
    int tid = threadIdx.x;
    int w = tid >> 5, lane = tid & 31;

    for (int idx = tid; idx < 1024; idx += 256)
        Qs[idx >> 5][idx & 31] = g_Q[n * 1024 + idx];
    __syncthreads();

    int o = obase + w;
    int g = 4 * n + (lane >> 3);
    int code = codes[o * 512 + g];
    float wv = codebooks[code * 8 + (lane & 7)];

    float acc = 0.f;
    #pragma unroll
    for (int kk = 0; kk < 32; kk++) {
        float wk = __shfl_sync(0xFFFFFFFFu, wv, kk);
        acc = fmaf(Qs[lane][kk], wk, acc);
    }
    acc *= scales[o];
    g_W2[(size_t)o * IN_F + n * 32 + lane] = __uint_as_float(cvt_rna_tf32(acc));
}

// ---------------------------------------------------------------------------
// Kernel 3: tf32 mma.sync GEMM   out[M,O] = x[M,K] @ W2[O,K]^T + bias
// CTA tile 128x128, KBLK=32, 4-stage cp.async pipeline, 8 warps (2x4),
// warp tile 64x32 = 4x4 of m16n8k8.
// SMEM layout per operand: [4 ksteps][128 rows][8 k] floats -> conflict-free
// fragment LDS without swizzle.
// ---------------------------------------------------------------------------
#define STAGES 4
#define KBLK   32
#define TM     128
#define TN     128
#define KITERS (IN_F / KBLK)            // 128
#define A_BYTES (TM * KBLK * 4)         // 16 KB
#define STAGE_BYTES (2 * A_BYTES)       // 32 KB

__device__ __forceinline__ void load_stage(char* sbase, const float* __restrict__ x,
                                           int mbase, int nbase, int kb, int tid)
{
    char* sA = sbase;
    char* sB = sbase + A_BYTES;
    #pragma unroll
    for (int it = 0; it < 4; it++) {
        int c   = it * 256 + tid;       // 0..1023 chunks of 16B
        int row = c >> 3;
        int jc  = c & 7;                // 16B chunk within 32-float row
        int ks  = jc >> 1;
        uint32_t soff = ks * 4096 + row * 32 + (jc & 1) * 16;
        cp16(sA + soff, x    + (size_t)(mbase + row) * IN_F + kb + jc * 4);
        cp16(sB + soff, g_W2 + (size_t)(nbase + row) * IN_F + kb + jc * 4);
    }
}

__global__ __launch_bounds__(256)
void gemm_kernel(const float* __restrict__ x, const float* __restrict__ bias,
                 float* __restrict__ out)
{
    extern __shared__ char smem[];

    int tid  = threadIdx.x;
    int wid  = tid >> 5, lane = tid & 31;
    int g    = lane >> 2, tig = lane & 3;
    int wm   = (wid >> 2) * 64;         // warp M offset (2 rows of warps)
    int wn   = (wid & 3) * 32;          // warp N offset (4 cols of warps)
    int nbase = blockIdx.x * TN;
    int mbase = blockIdx.y * TM;

    float acc[4][4][4];
    #pragma unroll
    for (int mi = 0; mi < 4; mi++)
        #pragma unroll
        for (int ni = 0; ni < 4; ni++)
            #pragma unroll
            for (int q = 0; q < 4; q++) acc[mi][ni][q] = 0.f;

    // Prologue: fill STAGES-1 stages
    #pragma unroll
    for (int s = 0; s < STAGES - 1; s++) {
        load_stage(smem + s * STAGE_BYTES, x, mbase, nbase, s * KBLK, tid);
        CP_COMMIT();
    }

    for (int k = 0; k < KITERS; k++) {
        CP_WAIT(STAGES - 2);
        __syncthreads();

        int kl = k + STAGES - 1;
        if (kl < KITERS)
            load_stage(smem + (kl & (STAGES - 1)) * STAGE_BYTES, x, mbase, nbase, kl * KBLK, tid);
        CP_COMMIT();

        const float* As = (const float*)(smem + (k & (STAGES - 1)) * STAGE_BYTES);
        const float* Bs = As + TM * KBLK;

        #pragma unroll
        for (int ks = 0; ks < 4; ks++) {
            const float* Ak = As + ks * 1024;
            const float* Bk = Bs + ks * 1024;
            uint32_t a[4][4], b[4][2];
            #pragma unroll
            for (int mi = 0; mi < 4; mi++) {
                int r = wm + mi * 16 + g;
                a[mi][0] = cvt_rna_tf32(Ak[r * 8 + tig]);
                a[mi][1] = cvt_rna_tf32(Ak[(r + 8) * 8 + tig]);
                a[mi][2] = cvt_rna_tf32(Ak[r * 8 + tig + 4]);
                a[mi][3] = cvt_rna_tf32(Ak[(r + 8) * 8 + tig + 4]);
            }
            #pragma unroll
            for (int ni = 0; ni < 4; ni++) {
                int r = wn + ni * 8 + g;
                b[ni][0] = __float_as_uint(Bk[r * 8 + tig]);
                b[ni][1] = __float_as_uint(Bk[r * 8 + tig + 4]);
            }
            #pragma unroll
            for (int mi = 0; mi < 4; mi++)
                #pragma unroll
                for (int ni = 0; ni < 4; ni++)
                    mma_tf32_16x8x8(acc[mi][ni], a[mi], b[ni]);
        }
    }

    // Epilogue: direct store + bias
    #pragma unroll
    for (int mi = 0; mi < 4; mi++) {
        int r0 = mbase + wm + mi * 16 + g;
        #pragma unroll
        for (int ni = 0; ni < 4; ni++) {
            int col = nbase + wn + ni * 8 + tig * 2;
            float2 bv = *(const float2*)(bias + col);
            float2 v0 = make_float2(acc[mi][ni][0] + bv.x, acc[mi][ni][1] + bv.y);
            float2 v1 = make_float2(acc[mi][ni][2] + bv.x, acc[mi][ni][3] + bv.y);
            *(float2*)(out + (size_t)r0 * OUT_F + col)       = v0;
            *(float2*)(out + (size_t)(r0 + 8) * OUT_F + col) = v1;
        }
    }
}

// ---------------------------------------------------------------------------
// Launch
// ---------------------------------------------------------------------------
extern "C" void kernel_launch(void* const* d_in, const int* in_sizes, int n_in,
                              void* d_out, int out_size)
{
    const float* x         = (const float*)d_in[0];
    const float* oft_r     = (const float*)d_in[1];
    const int*   codes     = (const int*)d_in[2];
    const float* codebooks = (const float*)d_in[3];
    const float* scales    = (const float*)d_in[4];
    const float* bias      = (const float*)d_in[5];
    float*       out       = (float*)d_out;

    cayley_kernel<<<NBLKS, dim3(32, 32)>>>(oft_r);
    dequant_kernel<<<dim3(NBLKS, OUT_F / 8), 256>>>(codes, codebooks, scales);

    int smem_bytes = STAGES * STAGE_BYTES;   // 128 KB
    cudaFuncSetAttribute(gemm_kernel, cudaFuncAttributeMaxDynamicSharedMemorySize, smem_bytes);
    gemm_kernel<<<dim3(OUT_F / TN, MROWS / TM), 256, smem_bytes>>>(x, bias, out);
}

// round 4
// speedup vs baseline: 3.0793x; 3.0793x over previous
#include <cuda_runtime.h>
#include <cuda_fp16.h>
#include <cstdint>

// ---------------------------------------------------------------------------
// Problem constants
// ---------------------------------------------------------------------------
#define IN_F   4096
#define OUT_F  4096
#define NBLKS  128      // IN_F / 32
#define MROWS  16384    // 4 * 4096 tokens

// Scratch (allocation-free rule: __device__ globals)
__device__ float  g_Q[NBLKS * 32 * 32];             // 512 KB
__device__ __half g_W2h[(size_t)OUT_F * IN_F];      // 32 MB  rotated+dequantized W, fp16
__device__ __half g_Xh[(size_t)MROWS * IN_F];       // 128 MB x in fp16

// ---------------------------------------------------------------------------
// Helpers
// ---------------------------------------------------------------------------
__device__ __forceinline__ uint32_t smem_u32(const void* p) {
    uint32_t a;
    asm("{ .reg .u64 t; cvta.to.shared.u64 t, %1; cvt.u32.u64 %0, t; }" : "=r"(a) : "l"(p));
    return a;
}

__device__ __forceinline__ void cp16(uint32_t s, const void* g) {
    asm volatile("cp.async.cg.shared.global [%0], [%1], 16;" :: "r"(s), "l"(g));
}
#define CP_COMMIT() asm volatile("cp.async.commit_group;" ::: "memory")
#define CP_WAIT(n)  asm volatile("cp.async.wait_group %0;" :: "n"(n) : "memory")

#define LDM_X4(R, addr) \
    asm volatile("ldmatrix.sync.aligned.m8n8.x4.shared.b16 {%0,%1,%2,%3}, [%4];" \
                 : "=r"((R)[0]), "=r"((R)[1]), "=r"((R)[2]), "=r"((R)[3]) : "r"(addr))

__device__ __forceinline__ void mma_f16(float c[4], const uint32_t a[4], uint32_t b0, uint32_t b1) {
    asm volatile(
        "mma.sync.aligned.m16n8k16.row.col.f32.f16.f16.f32 "
        "{%0,%1,%2,%3}, {%4,%5,%6,%7}, {%8,%9}, {%0,%1,%2,%3};"
        : "+f"(c[0]), "+f"(c[1]), "+f"(c[2]), "+f"(c[3])
        : "r"(a[0]), "r"(a[1]), "r"(a[2]), "r"(a[3]), "r"(b0), "r"(b1));
}

// ---------------------------------------------------------------------------
// Kernel 1: Cayley  Q = (I-S)^{-1}(I+S)   (Gauss-Jordan, diag-dominant, no pivot)
// ---------------------------------------------------------------------------
__global__ void cayley_kernel(const float* __restrict__ oft_r) {
    __shared__ float A[32][33];
    __shared__ float Bm[32][33];
    int n = blockIdx.x;
    int j = threadIdx.x, i = threadIdx.y;
    const float* R = oft_r + n * 1024;
    float s  = 0.5f * (R[i * 32 + j] - R[j * 32 + i]);
    float id = (i == j) ? 1.0f : 0.0f;
    A[i][j]  = id - s;
    Bm[i][j] = id + s;
    __syncthreads();
    for (int k = 0; k < 32; k++) {
        float fac = A[i][k] / A[k][k];
        __syncthreads();
        if (i != k) {
            A[i][j]  = fmaf(-fac, A[k][j],  A[i][j]);
            Bm[i][j] = fmaf(-fac, Bm[k][j], Bm[i][j]);
        }
        __syncthreads();
    }
    g_Q[n * 1024 + i * 32 + j] = Bm[i][j] / A[i][i];
}

// ---------------------------------------------------------------------------
// Kernel 2: dequant + fold rotation into W, output fp16 RN:
//   W2[o, n*32+j] = scales[o] * sum_k Q[n][j][k] * CB[codes[o, 4n + k/8]][k%8]
// ---------------------------------------------------------------------------
__global__ __launch_bounds__(256) void dequant_kernel(
    const int* __restrict__ codes, const float* __restrict__ codebooks,
    const float* __restrict__ scales)
{
    __shared__ float Qs[32][33];
    int n = blockIdx.x;                // 0..127
    int obase = blockIdx.y * 8;
    int tid = threadIdx.x;
    int w = tid >> 5, lane = tid & 31;

    for (int idx = tid; idx < 1024; idx += 256)
        Qs[idx >> 5][idx & 31] = g_Q[n * 1024 + idx];
    __syncthreads();

    int o = obase + w;
    int g = 4 * n + (lane >> 3);
    int code = codes[o * 512 + g];
    float wv = codebooks[code * 8 + (lane & 7)];

    float acc = 0.f;
    #pragma unroll
    for (int kk = 0; kk < 32; kk++) {
        float wk = __shfl_sync(0xFFFFFFFFu, wv, kk);
        acc = fmaf(Qs[lane][kk], wk, acc);
    }
    acc *= scales[o];
    g_W2h[(size_t)o * IN_F + n * 32 + lane] = __float2half_rn(acc);
}

// ---------------------------------------------------------------------------
// Kernel 2b: x -> fp16 (vectorized: 4 floats -> 4 halves per thread)
// ---------------------------------------------------------------------------
__global__ __launch_bounds__(256) void xconv_kernel(const float* __restrict__ x) {
    size_t i = ((size_t)blockIdx.x * 256 + threadIdx.x) * 4;
    float4 v = *(const float4*)(x + i);
    __half2 h0 = __floats2half2_rn(v.x, v.y);
    __half2 h1 = __floats2half2_rn(v.z, v.w);
    *(__half2*)(g_Xh + i)     = h0;
    *(__half2*)(g_Xh + i + 2) = h1;
}

// ---------------------------------------------------------------------------
// Kernel 3: fp16 mma.sync GEMM   out[M,O] = x[M,K] @ W2[O,K]^T + bias (fp32 acc)
// CTA tile 128x128, KBLK=32 (2 k16 steps), 4-stage cp.async pipeline,
// 8 warps (2x4), warp tile 64x32 = 4x4 of m16n8k16. ldmatrix.x4 fragments.
// SMEM row = 64B (32 fp16); 16B chunks XOR-swizzled: j ^= (row>>1)&3
//   -> conflict-free cp.async writes AND ldmatrix phases.
// ---------------------------------------------------------------------------
#define STAGES 4
#define KBLK   32
#define TM     128
#define TN     128
#define KITERS (IN_F / KBLK)            // 128
#define AST_BYTES (TM * KBLK * 2)       // 8 KB
#define STAGE_BYTES (2 * AST_BYTES)     // 16 KB

__device__ __forceinline__ uint32_t swz(int row, int j) {
    return (uint32_t)(row * 64 + ((j ^ ((row >> 1) & 3)) << 4));
}

__device__ __forceinline__ void load_stage(uint32_t sbase, int mbase, int nbase, int kb, int tid)
{
    uint32_t sA = sbase;
    uint32_t sB = sbase + AST_BYTES;
    #pragma unroll
    for (int h = 0; h < 2; h++) {
        int c   = h * 256 + tid;        // 0..511 chunks of 16B
        int row = c >> 2;
        int j   = c & 3;
        uint32_t soff = swz(row, j);
        cp16(sA + soff, g_Xh  + (size_t)(mbase + row) * IN_F + kb + j * 8);
        cp16(sB + soff, g_W2h + (size_t)(nbase + row) * IN_F + kb + j * 8);
    }
}

__global__ __launch_bounds__(256, 2)
void gemm_kernel(const float* __restrict__ bias, float* __restrict__ out)
{
    extern __shared__ char smem[];
    uint32_t sbase = smem_u32(smem);

    int tid  = threadIdx.x;
    int wid  = tid >> 5, lane = tid & 31;
    int g    = lane >> 2, tig = lane & 3;
    int lr   = lane & 7;                // ldmatrix row-within-matrix
    int q    = lane >> 3;               // ldmatrix matrix index 0..3
    int wm   = (wid >> 2) * 64;         // warp M offset
    int wn   = (wid & 3) * 32;          // warp N offset
    int nbase = blockIdx.x * TN;
    int mbase = blockIdx.y * TM;

    float acc[4][4][4];
    #pragma unroll
    for (int mi = 0; mi < 4; mi++)
        #pragma unroll
        for (int ni = 0; ni < 4; ni++)
            #pragma unroll
            for (int p = 0; p < 4; p++) acc[mi][ni][p] = 0.f;

    // Prologue: fill STAGES-1 stages
    #pragma unroll
    for (int s = 0; s < STAGES - 1; s++) {
        load_stage(sbase + s * STAGE_BYTES, mbase, nbase, s * KBLK, tid);
        CP_COMMIT();
    }

    for (int k = 0; k < KITERS; k++) {
        CP_WAIT(STAGES - 2);
        __syncthreads();

        int kl = k + STAGES - 1;
        if (kl < KITERS)
            load_stage(sbase + (kl & (STAGES - 1)) * STAGE_BYTES, mbase, nbase, kl * KBLK, tid);
        CP_COMMIT();

        uint32_t As = sbase + (k & (STAGES - 1)) * STAGE_BYTES;
        uint32_t Bs = As + AST_BYTES;

        #pragma unroll
        for (int s = 0; s < 2; s++) {           // two k16 steps
            int j = 2 * s + (q >> 1);           // this lane's 16B chunk
            uint32_t a[4][4], b[2][4];
            #pragma unroll
            for (int mi = 0; mi < 4; mi++) {
                int r = wm + mi * 16 + lr + (q & 1) * 8;
                LDM_X4(a[mi], As + swz(r, j));
            }
            #pragma unroll
            for (int p = 0; p < 2; p++) {
                int r = wn + p * 16 + lr + (q & 1) * 8;
                LDM_X4(b[p], Bs + swz(r, j));
            }
            // b[p] = {b0[2p], b0[2p+1], b1[2p], b1[2p+1]}
            #pragma unroll
            for (int mi = 0; mi < 4; mi++) {
                mma_f16(acc[mi][0], a[mi], b[0][0], b[0][2]);
                mma_f16(acc[mi][1], a[mi], b[0][1], b[0][3]);
                mma_f16(acc[mi][2], a[mi], b[1][0], b[1][2]);
                mma_f16(acc[mi][3], a[mi], b[1][1], b[1][3]);
            }
        }
    }

    // Epilogue: direct store + bias
    #pragma unroll
    for (int mi = 0; mi < 4; mi++) {
        int r0 = mbase + wm + mi * 16 + g;
        #pragma unroll
        for (int ni = 0; ni < 4; ni++) {
            int col = nbase + wn + ni * 8 + tig * 2;
            float2 bv = *(const float2*)(bias + col);
            float2 v0 = make_float2(acc[mi][ni][0] + bv.x, acc[mi][ni][1] + bv.y);
            float2 v1 = make_float2(acc[mi][ni][2] + bv.x, acc[mi][ni][3] + bv.y);
            *(float2*)(out + (size_t)r0 * OUT_F + col)       = v0;
            *(float2*)(out + (size_t)(r0 + 8) * OUT_F + col) = v1;
        }
    }
}

// ---------------------------------------------------------------------------
// Launch
// ---------------------------------------------------------------------------
extern "C" void kernel_launch(void* const* d_in, const int* in_sizes, int n_in,
                              void* d_out, int out_size)
{
    const float* x         = (const float*)d_in[0];
    const float* oft_r     = (const float*)d_in[1];
    const int*   codes     = (const int*)d_in[2];
    const float* codebooks = (const float*)d_in[3];
    const float* scales    = (const float*)d_in[4];
    const float* bias      = (const float*)d_in[5];
    float*       out       = (float*)d_out;

    cayley_kernel<<<NBLKS, dim3(32, 32)>>>(oft_r);
    xconv_kernel<<<(MROWS * (size_t)IN_F) / (256 * 4), 256>>>(x);
    dequant_kernel<<<dim3(NBLKS, OUT_F / 8), 256>>>(codes, codebooks, scales);

    int smem_bytes = STAGES * STAGE_BYTES;   // 64 KB
    cudaFuncSetAttribute(gemm_kernel, cudaFuncAttributeMaxDynamicSharedMemorySize, smem_bytes);
    gemm_kernel<<<dim3(OUT_F / TN, MROWS / TM), 256, smem_bytes>>>(bias, out);
}

// round 5
// speedup vs baseline: 3.2145x; 1.0439x over previous
#include <cuda_runtime.h>
#include <cuda_fp16.h>
#include <cstdint>

// ---------------------------------------------------------------------------
// Problem constants
// ---------------------------------------------------------------------------
#define IN_F   4096
#define OUT_F  4096
#define NBLKS  128      // IN_F / 32
#define MROWS  16384    // 4 * 4096 tokens

// Scratch (allocation-free rule: __device__ globals)
__device__ float  g_Q[NBLKS * 32 * 32];             // 512 KB
__device__ __half g_W2h[(size_t)OUT_F * IN_F];      // 32 MB  rotated+dequantized W, fp16
__device__ __half g_Xh[(size_t)MROWS * IN_F];       // 128 MB x in fp16

// ---------------------------------------------------------------------------
// Helpers
// ---------------------------------------------------------------------------
__device__ __forceinline__ uint32_t smem_u32(const void* p) {
    uint32_t a;
    asm("{ .reg .u64 t; cvta.to.shared.u64 t, %1; cvt.u32.u64 %0, t; }" : "=r"(a) : "l"(p));
    return a;
}

__device__ __forceinline__ void cp16(uint32_t s, const void* g) {
    asm volatile("cp.async.cg.shared.global [%0], [%1], 16;" :: "r"(s), "l"(g));
}
#define CP_COMMIT() asm volatile("cp.async.commit_group;" ::: "memory")
#define CP_WAIT(n)  asm volatile("cp.async.wait_group %0;" :: "n"(n) : "memory")

#define LDM_X4(R, addr) \
    asm volatile("ldmatrix.sync.aligned.m8n8.x4.shared.b16 {%0,%1,%2,%3}, [%4];" \
                 : "=r"((R)[0]), "=r"((R)[1]), "=r"((R)[2]), "=r"((R)[3]) : "r"(addr))

__device__ __forceinline__ void mma_f16(float c[4], const uint32_t a[4], uint32_t b0, uint32_t b1) {
    asm volatile(
        "mma.sync.aligned.m16n8k16.row.col.f32.f16.f16.f32 "
        "{%0,%1,%2,%3}, {%4,%5,%6,%7}, {%8,%9}, {%0,%1,%2,%3};"
        : "+f"(c[0]), "+f"(c[1]), "+f"(c[2]), "+f"(c[3])
        : "r"(a[0]), "r"(a[1]), "r"(a[2]), "r"(a[3]), "r"(b0), "r"(b1));
}

// ---------------------------------------------------------------------------
// Kernel 1: Cayley  Q = (I-S)^{-1}(I+S)   (Gauss-Jordan, diag-dominant, no pivot)
// ---------------------------------------------------------------------------
__global__ void cayley_kernel(const float* __restrict__ oft_r) {
    __shared__ float A[32][33];
    __shared__ float Bm[32][33];
    int n = blockIdx.x;
    int j = threadIdx.x, i = threadIdx.y;
    const float* R = oft_r + n * 1024;
    float s  = 0.5f * (R[i * 32 + j] - R[j * 32 + i]);
    float id = (i == j) ? 1.0f : 0.0f;
    A[i][j]  = id - s;
    Bm[i][j] = id + s;
    __syncthreads();
    for (int k = 0; k < 32; k++) {
        float fac = A[i][k] / A[k][k];
        __syncthreads();
        if (i != k) {
            A[i][j]  = fmaf(-fac, A[k][j],  A[i][j]);
            Bm[i][j] = fmaf(-fac, Bm[k][j], Bm[i][j]);
        }
        __syncthreads();
    }
    g_Q[n * 1024 + i * 32 + j] = Bm[i][j] / A[i][i];
}

// ---------------------------------------------------------------------------
// Kernel 2 (fused prep): blocks [0, XBLKS) convert x -> fp16;
// blocks [XBLKS, XBLKS+65536) dequant + fold rotation into W (fp16 out).
// Overlaps DRAM-bound conversion with L2-bound dequant.
// ---------------------------------------------------------------------------
#define XBLKS 65536     // MROWS*IN_F / (256*4)

__global__ __launch_bounds__(256) void prep_kernel(
    const float* __restrict__ x, const int* __restrict__ codes,
    const float* __restrict__ codebooks, const float* __restrict__ scales)
{
    __shared__ float Qs[32][33];
    int blk = blockIdx.x;
    if (blk < XBLKS) {
        size_t i = ((size_t)blk * 256 + threadIdx.x) * 4;
        float4 v = *(const float4*)(x + i);
        *(__half2*)(g_Xh + i)     = __floats2half2_rn(v.x, v.y);
        *(__half2*)(g_Xh + i + 2) = __floats2half2_rn(v.z, v.w);
        return;
    }
    blk -= XBLKS;
    int n = blk & 127;                 // 0..127
    int obase = (blk >> 7) * 8;
    int tid = threadIdx.x;
    int w = tid >> 5, lane = tid & 31;

    for (int idx = tid; idx < 1024; idx += 256)
        Qs[idx >> 5][idx & 31] = g_Q[n * 1024 + idx];
    __syncthreads();

    int o = obase + w;
    int grp = 4 * n + (lane >> 3);
    int code = codes[o * 512 + grp];
    float wv = codebooks[code * 8 + (lane & 7)];

    float acc = 0.f;
    #pragma unroll
    for (int kk = 0; kk < 32; kk++) {
        float wk = __shfl_sync(0xFFFFFFFFu, wv, kk);
        acc = fmaf(Qs[lane][kk], wk, acc);
    }
    acc *= scales[o];
    g_W2h[(size_t)o * IN_F + n * 32 + lane] = __float2half_rn(acc);
}

// ---------------------------------------------------------------------------
// Kernel 3: fp16 mma.sync GEMM   out[M,O] = x[M,K] @ W2[O,K]^T + bias (fp32 acc)
// CTA 128x128, KBLK=32 (2 k16 substeps), 4-stage cp.async pipeline, 8 warps
// (2x4), warp tile 64x32. Register-level fragment double-buffering:
// substep s+1 fragments prefetched before substep-s MMAs; next-stage substep-0
// fragments prefetched right after the barrier, before substep-1 MMAs.
// Swizzle offsets hoisted (swz(r+16m,j) = swz(r,j) + 1024m).
// ---------------------------------------------------------------------------
#define STAGES 4
#define KBLK   32
#define TM     128
#define TN     128
#define KITERS (IN_F / KBLK)            // 128
#define AST_BYTES (TM * KBLK * 2)       // 8 KB
#define STAGE_BYTES (2 * AST_BYTES)     // 16 KB

__device__ __forceinline__ uint32_t swz(int row, int j) {
    return (uint32_t)(row * 64 + ((j ^ ((row >> 1) & 3)) << 4));
}

__device__ __forceinline__ void stage_fill(uint32_t sb,
        const __half* gA0, const __half* gA1, const __half* gB0, const __half* gB1,
        uint32_t so0, uint32_t so1, int kb)
{
    cp16(sb + so0,             gA0 + kb);
    cp16(sb + so1,             gA1 + kb);
    cp16(sb + AST_BYTES + so0, gB0 + kb);
    cp16(sb + AST_BYTES + so1, gB1 + kb);
}

__device__ __forceinline__ void frag_load(uint32_t a[4][4], uint32_t b[2][4],
                                          uint32_t sb, uint32_t aoff, uint32_t boff)
{
    #pragma unroll
    for (int mi = 0; mi < 4; mi++) LDM_X4(a[mi], sb + aoff + mi * 1024);
    #pragma unroll
    for (int p = 0; p < 2; p++)   LDM_X4(b[p], sb + AST_BYTES + boff + p * 1024);
}

__device__ __forceinline__ void mma_block(float acc[4][4][4],
                                          const uint32_t a[4][4], const uint32_t b[2][4])
{
    #pragma unroll
    for (int mi = 0; mi < 4; mi++) {
        mma_f16(acc[mi][0], a[mi], b[0][0], b[0][2]);
        mma_f16(acc[mi][1], a[mi], b[0][1], b[0][3]);
        mma_f16(acc[mi][2], a[mi], b[1][0], b[1][2]);
        mma_f16(acc[mi][3], a[mi], b[1][1], b[1][3]);
    }
}

__global__ __launch_bounds__(256, 2)
void gemm_kernel(const float* __restrict__ bias, float* __restrict__ out)
{
    extern __shared__ char smem[];
    uint32_t sbase = smem_u32(smem);

    int tid  = threadIdx.x;
    int wid  = tid >> 5, lane = tid & 31;
    int g    = lane >> 2, tig = lane & 3;
    int lr   = lane & 7;                // ldmatrix row-within-matrix
    int q    = lane >> 3;               // ldmatrix matrix index 0..3
    int wm   = (wid >> 2) * 64;         // warp M offset
    int wn   = (wid & 3) * 32;          // warp N offset
    int nbase = blockIdx.x * TN;
    int mbase = blockIdx.y * TM;

    // Hoisted ldmatrix offsets: substep s uses chunk j = 2s + (q>>1).
    int ra = wm + lr + ((q & 1) << 3);
    int rb = wn + lr + ((q & 1) << 3);
    int ja = q >> 1;
    uint32_t aoff0 = swz(ra, ja);
    uint32_t aoff1 = swz(ra, ja + 2);
    uint32_t boff0 = swz(rb, ja);
    uint32_t boff1 = swz(rb, ja + 2);

    // Cached global pointers: 2 chunks per operand per stage per thread.
    int r0 = tid >> 2, j0 = tid & 3;
    const __half* gA0 = g_Xh  + (size_t)(mbase + r0) * IN_F + j0 * 8;
    const __half* gA1 = gA0 + (size_t)64 * IN_F;
    const __half* gB0 = g_W2h + (size_t)(nbase + r0) * IN_F + j0 * 8;
    const __half* gB1 = gB0 + (size_t)64 * IN_F;
    uint32_t so0 = swz(r0, j0), so1 = swz(r0 + 64, j0);

    float acc[4][4][4];
    #pragma unroll
    for (int mi = 0; mi < 4; mi++)
        #pragma unroll
        for (int ni = 0; ni < 4; ni++)
            #pragma unroll
            for (int p = 0; p < 4; p++) acc[mi][ni][p] = 0.f;

    // Prologue: fill STAGES-1 stages
    #pragma unroll
    for (int s = 0; s < STAGES - 1; s++) {
        stage_fill(sbase + s * STAGE_BYTES, gA0, gA1, gB0, gB1, so0, so1, s * KBLK);
        CP_COMMIT();
    }
    CP_WAIT(STAGES - 2);
    __syncthreads();

    uint32_t a[2][4][4], b[2][2][4];
    frag_load(a[0], b[0], sbase, aoff0, boff0);

    for (int k = 0; k < KITERS; k++) {
        uint32_t sb = sbase + (k & (STAGES - 1)) * STAGE_BYTES;

        // Prefetch substep-1 fragments of the current stage.
        frag_load(a[1], b[1], sb, aoff1, boff1);

        // Issue next stage's global loads (buffer (k-1)&3; its reads finished
        // before the previous iteration's barrier).
        int kl = k + STAGES - 1;
        if (kl < KITERS)
            stage_fill(sbase + (kl & (STAGES - 1)) * STAGE_BYTES,
                       gA0, gA1, gB0, gB1, so0, so1, kl * KBLK);
        CP_COMMIT();

        mma_block(acc, a[0], b[0]);                 // substep 0

        CP_WAIT(STAGES - 2);                        // stage k+1 landed
        __syncthreads();

        if (k + 1 < KITERS)                         // prefetch next stage substep 0
            frag_load(a[0], b[0], sbase + ((k + 1) & (STAGES - 1)) * STAGE_BYTES,
                      aoff0, boff0);

        mma_block(acc, a[1], b[1]);                 // substep 1
    }

    // Epilogue: direct store + bias
    #pragma unroll
    for (int mi = 0; mi < 4; mi++) {
        int r = mbase + wm + mi * 16 + g;
        #pragma unroll
        for (int ni = 0; ni < 4; ni++) {
            int col = nbase + wn + ni * 8 + tig * 2;
            float2 bv = *(const float2*)(bias + col);
            float2 v0 = make_float2(acc[mi][ni][0] + bv.x, acc[mi][ni][1] + bv.y);
            float2 v1 = make_float2(acc[mi][ni][2] + bv.x, acc[mi][ni][3] + bv.y);
            *(float2*)(out + (size_t)r * OUT_F + col)       = v0;
            *(float2*)(out + (size_t)(r + 8) * OUT_F + col) = v1;
        }
    }
}

// ---------------------------------------------------------------------------
// Launch
// ---------------------------------------------------------------------------
extern "C" void kernel_launch(void* const* d_in, const int* in_sizes, int n_in,
                              void* d_out, int out_size)
{
    const float* x         = (const float*)d_in[0];
    const float* oft_r     = (const float*)d_in[1];
    const int*   codes     = (const int*)d_in[2];
    const float* codebooks = (const float*)d_in[3];
    const float* scales    = (const float*)d_in[4];
    const float* bias      = (const float*)d_in[5];
    float*       out       = (float*)d_out;

    cayley_kernel<<<NBLKS, dim3(32, 32)>>>(oft_r);
    prep_kernel<<<XBLKS + NBLKS * (OUT_F / 8), 256>>>(x, codes, codebooks, scales);

    int smem_bytes = STAGES * STAGE_BYTES;   // 64 KB
    cudaFuncSetAttribute(gemm_kernel, cudaFuncAttributeMaxDynamicSharedMemorySize, smem_bytes);
    gemm_kernel<<<dim3(OUT_F / TN, MROWS / TM), 256, smem_bytes>>>(bias, out);
}

// round 6
// speedup vs baseline: 3.6794x; 1.1446x over previous
#include <cuda_runtime.h>
#include <cuda_fp16.h>
#include <cstdint>

// ---------------------------------------------------------------------------
// Problem constants
// ---------------------------------------------------------------------------
#define IN_F   4096
#define OUT_F  4096
#define NBLKS  128      // IN_F / 32
#define MROWS  16384    // 4 * 4096 tokens

// Scratch (allocation-free rule: __device__ globals)
__device__ float  g_Q[NBLKS * 32 * 32];             // 512 KB
__device__ __half g_W2h[(size_t)OUT_F * IN_F];      // 32 MB  rotated+dequantized W, fp16
__device__ __half g_Xh[(size_t)MROWS * IN_F];       // 128 MB x in fp16

// ---------------------------------------------------------------------------
// Helpers
// ---------------------------------------------------------------------------
__device__ __forceinline__ uint32_t smem_u32(const void* p) {
    uint32_t a;
    asm("{ .reg .u64 t; cvta.to.shared.u64 t, %1; cvt.u32.u64 %0, t; }" : "=r"(a) : "l"(p));
    return a;
}

__device__ __forceinline__ void cp16(uint32_t s, const void* g) {
    asm volatile("cp.async.cg.shared.global [%0], [%1], 16;" :: "r"(s), "l"(g));
}
#define CP_COMMIT() asm volatile("cp.async.commit_group;" ::: "memory")
#define CP_WAIT(n)  asm volatile("cp.async.wait_group %0;" :: "n"(n) : "memory")

#define LDM_X4(R, addr) \
    asm volatile("ldmatrix.sync.aligned.m8n8.x4.shared.b16 {%0,%1,%2,%3}, [%4];" \
                 : "=r"((R)[0]), "=r"((R)[1]), "=r"((R)[2]), "=r"((R)[3]) : "r"(addr))

__device__ __forceinline__ void mma_f16(float c[4], const uint32_t a[4], uint32_t b0, uint32_t b1) {
    asm volatile(
        "mma.sync.aligned.m16n8k16.row.col.f32.f16.f16.f32 "
        "{%0,%1,%2,%3}, {%4,%5,%6,%7}, {%8,%9}, {%0,%1,%2,%3};"
        : "+f"(c[0]), "+f"(c[1]), "+f"(c[2]), "+f"(c[3])
        : "r"(a[0]), "r"(a[1]), "r"(a[2]), "r"(a[3]), "r"(b0), "r"(b1));
}

// ---------------------------------------------------------------------------
// Kernel 1: Cayley  Q = (I-S)^{-1}(I+S)   (Gauss-Jordan, diag-dominant, no pivot)
// ---------------------------------------------------------------------------
__global__ void cayley_kernel(const float* __restrict__ oft_r) {
    __shared__ float A[32][33];
    __shared__ float Bm[32][33];
    int n = blockIdx.x;
    int j = threadIdx.x, i = threadIdx.y;
    const float* R = oft_r + n * 1024;
    float s  = 0.5f * (R[i * 32 + j] - R[j * 32 + i]);
    float id = (i == j) ? 1.0f : 0.0f;
    A[i][j]  = id - s;
    Bm[i][j] = id + s;
    __syncthreads();
    for (int k = 0; k < 32; k++) {
        float fac = A[i][k] / A[k][k];
        __syncthreads();
        if (i != k) {
            A[i][j]  = fmaf(-fac, A[k][j],  A[i][j]);
            Bm[i][j] = fmaf(-fac, Bm[k][j], Bm[i][j]);
        }
        __syncthreads();
    }
    g_Q[n * 1024 + i * 32 + j] = Bm[i][j] / A[i][i];
}

// ---------------------------------------------------------------------------
// Kernel 2 (fused prep): blocks [0, XBLKS) convert x -> fp16;
// blocks [XBLKS, XBLKS+65536) dequant + fold rotation into W (fp16 out).
// ---------------------------------------------------------------------------
#define XBLKS 65536     // MROWS*IN_F / (256*4)

__global__ __launch_bounds__(256) void prep_kernel(
    const float* __restrict__ x, const int* __restrict__ codes,
    const float* __restrict__ codebooks, const float* __restrict__ scales)
{
    __shared__ float Qs[32][33];
    int blk = blockIdx.x;
    if (blk < XBLKS) {
        size_t i = ((size_t)blk * 256 + threadIdx.x) * 4;
        float4 v = *(const float4*)(x + i);
        *(__half2*)(g_Xh + i)     = __floats2half2_rn(v.x, v.y);
        *(__half2*)(g_Xh + i + 2) = __floats2half2_rn(v.z, v.w);
        return;
    }
    blk -= XBLKS;
    int n = blk & 127;                 // 0..127
    int obase = (blk >> 7) * 8;
    int tid = threadIdx.x;
    int w = tid >> 5, lane = tid & 31;

    for (int idx = tid; idx < 1024; idx += 256)
        Qs[idx >> 5][idx & 31] = g_Q[n * 1024 + idx];
    __syncthreads();

    int o = obase + w;
    int grp = 4 * n + (lane >> 3);
    int code = codes[o * 512 + grp];
    float wv = codebooks[code * 8 + (lane & 7)];

    float acc = 0.f;
    #pragma unroll
    for (int kk = 0; kk < 32; kk++) {
        float wk = __shfl_sync(0xFFFFFFFFu, wv, kk);
        acc = fmaf(Qs[lane][kk], wk, acc);
    }
    acc *= scales[o];
    g_W2h[(size_t)o * IN_F + n * 32 + lane] = __float2half_rn(acc);
}

// ---------------------------------------------------------------------------
// Kernel 3: fp16 mma.sync GEMM   out[M,O] = x[M,K] @ W2[O,K]^T + bias (fp32 acc)
// CTA 128x128, KBLK=32 (2 k16 substeps), 4-stage cp.async pipeline, 8 warps
// (2x4), warp tile 64x32. Register-level fragment double-buffering.
// __launch_bounds__(256, 1): 255-reg budget -> NO spills (R5 lesson: the
// (256,2) 128-reg cap spilled the double-buffered fragments to local).
// ---------------------------------------------------------------------------
#define STAGES 4
#define KBLK   32
#define TM     128
#define TN     128
#define KITERS (IN_F / KBLK)            // 128
#define AST_BYTES (TM * KBLK * 2)       // 8 KB
#define STAGE_BYTES (2 * AST_BYTES)     // 16 KB

__device__ __forceinline__ uint32_t swz(int row, int j) {
    return (uint32_t)(row * 64 + ((j ^ ((row >> 1) & 3)) << 4));
}

__device__ __forceinline__ void stage_fill(uint32_t sb,
        const __half* gA0, const __half* gA1, const __half* gB0, const __half* gB1,
        uint32_t so0, uint32_t so1, int kb)
{
    cp16(sb + so0,             gA0 + kb);
    cp16(sb + so1,             gA1 + kb);
    cp16(sb + AST_BYTES + so0, gB0 + kb);
    cp16(sb + AST_BYTES + so1, gB1 + kb);
}

__device__ __forceinline__ void frag_load(uint32_t a[4][4], uint32_t b[2][4],
                                          uint32_t sb, uint32_t aoff, uint32_t boff)
{
    #pragma unroll
    for (int mi = 0; mi < 4; mi++) LDM_X4(a[mi], sb + aoff + mi * 1024);
    #pragma unroll
    for (int p = 0; p < 2; p++)   LDM_X4(b[p], sb + AST_BYTES + boff + p * 1024);
}

__device__ __forceinline__ void mma_block(float acc[4][4][4],
                                          const uint32_t a[4][4], const uint32_t b[2][4])
{
    #pragma unroll
    for (int mi = 0; mi < 4; mi++) {
        mma_f16(acc[mi][0], a[mi], b[0][0], b[0][2]);
        mma_f16(acc[mi][1], a[mi], b[0][1], b[0][3]);
        mma_f16(acc[mi][2], a[mi], b[1][0], b[1][2]);
        mma_f16(acc[mi][3], a[mi], b[1][1], b[1][3]);
    }
}

__global__ __launch_bounds__(256, 1)
void gemm_kernel(const float* __restrict__ bias, float* __restrict__ out)
{
    extern __shared__ char smem[];
    uint32_t sbase = smem_u32(smem);

    int tid  = threadIdx.x;
    int wid  = tid >> 5, lane = tid & 31;
    int g    = lane >> 2, tig = lane & 3;
    int lr   = lane & 7;                // ldmatrix row-within-matrix
    int q    = lane >> 3;               // ldmatrix matrix index 0..3
    int wm   = (wid >> 2) * 64;         // warp M offset
    int wn   = (wid & 3) * 32;          // warp N offset
    int nbase = blockIdx.x * TN;
    int mbase = blockIdx.y * TM;

    // Hoisted ldmatrix offsets: substep s uses chunk j = 2s + (q>>1).
    int ra = wm + lr + ((q & 1) << 3);
    int rb = wn + lr + ((q & 1) << 3);
    int ja = q >> 1;
    uint32_t aoff0 = swz(ra, ja);
    uint32_t aoff1 = swz(ra, ja + 2);
    uint32_t boff0 = swz(rb, ja);
    uint32_t boff1 = swz(rb, ja + 2);

    // Cached global pointers: 2 chunks per operand per stage per thread.
    int r0 = tid >> 2, j0 = tid & 3;
    const __half* gA0 = g_Xh  + (size_t)(mbase + r0) * IN_F + j0 * 8;
    const __half* gA1 = gA0 + (size_t)64 * IN_F;
    const __half* gB0 = g_W2h + (size_t)(nbase + r0) * IN_F + j0 * 8;
    const __half* gB1 = gB0 + (size_t)64 * IN_F;
    uint32_t so0 = swz(r0, j0), so1 = swz(r0 + 64, j0);

    float acc[4][4][4];
    #pragma unroll
    for (int mi = 0; mi < 4; mi++)
        #pragma unroll
        for (int ni = 0; ni < 4; ni++)
            #pragma unroll
            for (int p = 0; p < 4; p++) acc[mi][ni][p] = 0.f;

    // Prologue: fill STAGES-1 stages
    #pragma unroll
    for (int s = 0; s < STAGES - 1; s++) {
        stage_fill(sbase + s * STAGE_BYTES, gA0, gA1, gB0, gB1, so0, so1, s * KBLK);
        CP_COMMIT();
    }
    CP_WAIT(STAGES - 2);
    __syncthreads();

    uint32_t a[2][4][4], b[2][2][4];
    frag_load(a[0], b[0], sbase, aoff0, boff0);

    for (int k = 0; k < KITERS; k++) {
        uint32_t sb = sbase + (k & (STAGES - 1)) * STAGE_BYTES;

        // Prefetch substep-1 fragments of the current stage.
        frag_load(a[1], b[1], sb, aoff1, boff1);

        // Issue next stage's global loads into buffer (k-1)&3 (its readers
        // all passed the previous iteration's barrier).
        int kl = k + STAGES - 1;
        if (kl < KITERS)
            stage_fill(sbase + (kl & (STAGES - 1)) * STAGE_BYTES,
                       gA0, gA1, gB0, gB1, so0, so1, kl * KBLK);
        CP_COMMIT();

        mma_block(acc, a[0], b[0]);                 // substep 0

        CP_WAIT(STAGES - 2);                        // stage k+1 landed
        __syncthreads();

        if (k + 1 < KITERS)                         // prefetch next stage substep 0
            frag_load(a[0], b[0], sbase + ((k + 1) & (STAGES - 1)) * STAGE_BYTES,
                      aoff0, boff0);

        mma_block(acc, a[1], b[1]);                 // substep 1
    }

    // Epilogue: direct store + bias
    #pragma unroll
    for (int mi = 0; mi < 4; mi++) {
        int r = mbase + wm + mi * 16 + g;
        #pragma unroll
        for (int ni = 0; ni < 4; ni++) {
            int col = nbase + wn + ni * 8 + tig * 2;
            float2 bv = *(const float2*)(bias + col);
            float2 v0 = make_float2(acc[mi][ni][0] + bv.x, acc[mi][ni][1] + bv.y);
            float2 v1 = make_float2(acc[mi][ni][2] + bv.x, acc[mi][ni][3] + bv.y);
            *(float2*)(out + (size_t)r * OUT_F + col)       = v0;
            *(float2*)(out + (size_t)(r + 8) * OUT_F + col) = v1;
        }
    }
}

// ---------------------------------------------------------------------------
// Launch
// ---------------------------------------------------------------------------
extern "C" void kernel_launch(void* const* d_in, const int* in_sizes, int n_in,
                              void* d_out, int out_size)
{
    const float* x         = (const float*)d_in[0];
    const float* oft_r     = (const float*)d_in[1];
    const int*   codes     = (const int*)d_in[2];
    const float* codebooks = (const float*)d_in[3];
    const float* scales    = (const float*)d_in[4];
    const float* bias      = (const float*)d_in[5];
    float*       out       = (float*)d_out;

    cayley_kernel<<<NBLKS, dim3(32, 32)>>>(oft_r);
    prep_kernel<<<XBLKS + NBLKS * (OUT_F / 8), 256>>>(x, codes, codebooks, scales);

    int smem_bytes = STAGES * STAGE_BYTES;   // 64 KB
    cudaFuncSetAttribute(gemm_kernel, cudaFuncAttributeMaxDynamicSharedMemorySize, smem_bytes);
    gemm_kernel<<<dim3(OUT_F / TN, MROWS / TM), 256, smem_bytes>>>(bias, out);
}

// round 7
// speedup vs baseline: 3.8642x; 1.0502x over previous
#include <cuda_runtime.h>
#include <cuda_fp16.h>
#include <cstdint>

// ---------------------------------------------------------------------------
// Problem constants
// ---------------------------------------------------------------------------
#define IN_F   4096
#define OUT_F  4096
#define NBLKS  128      // IN_F / 32
#define MROWS  16384    // 4 * 4096 tokens

// Scratch (allocation-free rule: __device__ globals)
__device__ float  g_Q[NBLKS * 32 * 32];             // 512 KB
__device__ __half g_W2h[(size_t)OUT_F * IN_F];      // 32 MB  rotated+dequantized W, fp16
__device__ __half g_Xh[(size_t)MROWS * IN_F];       // 128 MB x in fp16

// ---------------------------------------------------------------------------
// Helpers
// ---------------------------------------------------------------------------
__device__ __forceinline__ uint32_t smem_u32(const void* p) {
    uint32_t a;
    asm("{ .reg .u64 t; cvta.to.shared.u64 t, %1; cvt.u32.u64 %0, t; }" : "=r"(a) : "l"(p));
    return a;
}

__device__ __forceinline__ void cp16(uint32_t s, const void* g) {
    asm volatile("cp.async.cg.shared.global [%0], [%1], 16;" :: "r"(s), "l"(g));
}
#define CP_COMMIT() asm volatile("cp.async.commit_group;" ::: "memory")
#define CP_WAIT(n)  asm volatile("cp.async.wait_group %0;" :: "n"(n) : "memory")

#define LDM_X4(R, addr) \
    asm volatile("ldmatrix.sync.aligned.m8n8.x4.shared.b16 {%0,%1,%2,%3}, [%4];" \
                 : "=r"((R)[0]), "=r"((R)[1]), "=r"((R)[2]), "=r"((R)[3]) : "r"(addr))

__device__ __forceinline__ void mma_f16(float c[4], const uint32_t a[4], uint32_t b0, uint32_t b1) {
    asm volatile(
        "mma.sync.aligned.m16n8k16.row.col.f32.f16.f16.f32 "
        "{%0,%1,%2,%3}, {%4,%5,%6,%7}, {%8,%9}, {%0,%1,%2,%3};"
        : "+f"(c[0]), "+f"(c[1]), "+f"(c[2]), "+f"(c[3])
        : "r"(a[0]), "r"(a[1]), "r"(a[2]), "r"(a[3]), "r"(b0), "r"(b1));
}

// ---------------------------------------------------------------------------
// Kernel 1: Cayley  Q = (I-S)^{-1}(I+S)   (Gauss-Jordan, diag-dominant, no pivot)
// ---------------------------------------------------------------------------
__global__ void cayley_kernel(const float* __restrict__ oft_r) {
    __shared__ float A[32][33];
    __shared__ float Bm[32][33];
    int n = blockIdx.x;
    int j = threadIdx.x, i = threadIdx.y;
    const float* R = oft_r + n * 1024;
    float s  = 0.5f * (R[i * 32 + j] - R[j * 32 + i]);
    float id = (i == j) ? 1.0f : 0.0f;
    A[i][j]  = id - s;
    Bm[i][j] = id + s;
    __syncthreads();
    for (int k = 0; k < 32; k++) {
        float fac = A[i][k] / A[k][k];
        __syncthreads();
        if (i != k) {
            A[i][j]  = fmaf(-fac, A[k][j],  A[i][j]);
            Bm[i][j] = fmaf(-fac, Bm[k][j], Bm[i][j]);
        }
        __syncthreads();
    }
    g_Q[n * 1024 + i * 32 + j] = Bm[i][j] / A[i][i];
}

// ---------------------------------------------------------------------------
// Kernel 2 (fused prep): blocks [0, XBLKS) convert x -> fp16;
// blocks [XBLKS, XBLKS+65536) dequant + fold rotation into W (fp16 out).
// ---------------------------------------------------------------------------
#define XBLKS 65536     // MROWS*IN_F / (256*4)

__global__ __launch_bounds__(256) void prep_kernel(
    const float* __restrict__ x, const int* __restrict__ codes,
    const float* __restrict__ codebooks, const float* __restrict__ scales)
{
    __shared__ float Qs[32][33];
    int blk = blockIdx.x;
    if (blk < XBLKS) {
        size_t i = ((size_t)blk * 256 + threadIdx.x) * 4;
        float4 v = *(const float4*)(x + i);
        *(__half2*)(g_Xh + i)     = __floats2half2_rn(v.x, v.y);
        *(__half2*)(g_Xh + i + 2) = __floats2half2_rn(v.z, v.w);
        return;
    }
    blk -= XBLKS;
    int n = blk & 127;                 // 0..127
    int obase = (blk >> 7) * 8;
    int tid = threadIdx.x;
    int w = tid >> 5, lane = tid & 31;

    for (int idx = tid; idx < 1024; idx += 256)
        Qs[idx >> 5][idx & 31] = g_Q[n * 1024 + idx];
    __syncthreads();

    int o = obase + w;
    int grp = 4 * n + (lane >> 3);
    int code = codes[o * 512 + grp];
    float wv = codebooks[code * 8 + (lane & 7)];

    float acc = 0.f;
    #pragma unroll
    for (int kk = 0; kk < 32; kk++) {
        float wk = __shfl_sync(0xFFFFFFFFu, wv, kk);
        acc = fmaf(Qs[lane][kk], wk, acc);
    }
    acc *= scales[o];
    g_W2h[(size_t)o * IN_F + n * 32 + lane] = __float2half_rn(acc);
}

// ---------------------------------------------------------------------------
// Kernel 3: fp16 mma.sync GEMM   out[M,O] = x[M,K] @ W2[O,K]^T + bias (fp32 acc)
// CTA 128x256, KBLK=32 (2 k16 substeps), 4-stage cp.async pipeline, 8 warps
// (2x4), warp tile 64x64 = 4x8 of m16n8k16. Register-level fragment
// double-buffering; LDSM:HMMA ratio 0.25 (vs 0.375 at 64x32 warp tile).
// __launch_bounds__(256, 1): ~225 regs, no spills under 255 cap.
// ---------------------------------------------------------------------------
#define STAGES 4
#define KBLK   32
#define TM     128
#define TN     256
#define KITERS (IN_F / KBLK)            // 128
#define A_BYTES (TM * KBLK * 2)         // 8 KB
#define B_BYTES (TN * KBLK * 2)         // 16 KB
#define STAGE_BYTES (A_BYTES + B_BYTES) // 24 KB

__device__ __forceinline__ uint32_t swz(int row, int j) {
    return (uint32_t)(row * 64 + ((j ^ ((row >> 1) & 3)) << 4));
}

__device__ __forceinline__ void stage_fill(uint32_t sb,
        const __half* gA0, const __half* gA1,
        const __half* gB0, const __half* gB1, const __half* gB2, const __half* gB3,
        uint32_t so0, uint32_t so1, int kb)
{
    // A: 128 rows x 4 chunks = 512 -> 2 per thread (rows r0, r0+64)
    cp16(sb + so0, gA0 + kb);
    cp16(sb + so1, gA1 + kb);
    // B: 256 rows x 4 chunks = 1024 -> 4 per thread (rows r0, +64, +128, +192)
    uint32_t bb = sb + A_BYTES;
    cp16(bb + so0,         gB0 + kb);
    cp16(bb + so0 + 4096,  gB1 + kb);
    cp16(bb + so0 + 8192,  gB2 + kb);
    cp16(bb + so0 + 12288, gB3 + kb);
}

__device__ __forceinline__ void frag_load(uint32_t a[4][4], uint32_t b[4][4],
                                          uint32_t sb, uint32_t aoff, uint32_t boff)
{
    #pragma unroll
    for (int mi = 0; mi < 4; mi++) LDM_X4(a[mi], sb + aoff + mi * 1024);
    #pragma unroll
    for (int p = 0; p < 4; p++)    LDM_X4(b[p], sb + A_BYTES + boff + p * 1024);
}

__device__ __forceinline__ void mma_block(float acc[4][8][4],
                                          const uint32_t a[4][4], const uint32_t b[4][4])
{
    #pragma unroll
    for (int mi = 0; mi < 4; mi++)
        #pragma unroll
        for (int p = 0; p < 4; p++) {
            mma_f16(acc[mi][2 * p],     a[mi], b[p][0], b[p][2]);
            mma_f16(acc[mi][2 * p + 1], a[mi], b[p][1], b[p][3]);
        }
}

__global__ __launch_bounds__(256, 1)
void gemm_kernel(const float* __restrict__ bias, float* __restrict__ out)
{
    extern __shared__ char smem[];
    uint32_t sbase = smem_u32(smem);

    int tid  = threadIdx.x;
    int wid  = tid >> 5, lane = tid & 31;
    int g    = lane >> 2, tig = lane & 3;
    int lr   = lane & 7;                // ldmatrix row-within-matrix
    int q    = lane >> 3;               // ldmatrix matrix index 0..3
    int wm   = (wid >> 2) * 64;         // warp M offset (2 rows of warps)
    int wn   = (wid & 3) * 64;          // warp N offset (4 cols of warps)
    int nbase = blockIdx.x * TN;
    int mbase = blockIdx.y * TM;

    // Hoisted ldmatrix offsets: substep s uses 16B chunk j = 2s + (q>>1).
    int ra = wm + lr + ((q & 1) << 3);
    int rb = wn + lr + ((q & 1) << 3);
    int ja = q >> 1;
    uint32_t aoff0 = swz(ra, ja);
    uint32_t aoff1 = swz(ra, ja + 2);
    uint32_t boff0 = swz(rb, ja);
    uint32_t boff1 = swz(rb, ja + 2);

    // Cached global pointers (per-thread chunks).
    int r0 = tid >> 2, j0 = tid & 3;
    const __half* gA0 = g_Xh  + (size_t)(mbase + r0) * IN_F + j0 * 8;
    const __half* gA1 = gA0 + (size_t)64 * IN_F;
    const __half* gB0 = g_W2h + (size_t)(nbase + r0) * IN_F + j0 * 8;
    const __half* gB1 = gB0 + (size_t)64  * IN_F;
    const __half* gB2 = gB0 + (size_t)128 * IN_F;
    const __half* gB3 = gB0 + (size_t)192 * IN_F;
    uint32_t so0 = swz(r0, j0), so1 = swz(r0 + 64, j0);

    float acc[4][8][4];
    #pragma unroll
    for (int mi = 0; mi < 4; mi++)
        #pragma unroll
        for (int ni = 0; ni < 8; ni++)
            #pragma unroll
            for (int p = 0; p < 4; p++) acc[mi][ni][p] = 0.f;

    // Prologue: fill STAGES-1 stages
    #pragma unroll
    for (int s = 0; s < STAGES - 1; s++) {
        stage_fill(sbase + s * STAGE_BYTES, gA0, gA1, gB0, gB1, gB2, gB3, so0, so1, s * KBLK);
        CP_COMMIT();
    }
    CP_WAIT(STAGES - 2);
    __syncthreads();

    uint32_t a[2][4][4], b[2][4][4];
    frag_load(a[0], b[0], sbase, aoff0, boff0);

    for (int k = 0; k < KITERS; k++) {
        uint32_t sb = sbase + (k & (STAGES - 1)) * STAGE_BYTES;

        // Prefetch substep-1 fragments of the current stage.
        frag_load(a[1], b[1], sb, aoff1, boff1);

        // Issue next stage's global loads into buffer (k-1)&3.
        int kl = k + STAGES - 1;
        if (kl < KITERS)
            stage_fill(sbase + (kl & (STAGES - 1)) * STAGE_BYTES,
                       gA0, gA1, gB0, gB1, gB2, gB3, so0, so1, kl * KBLK);
        CP_COMMIT();

        mma_block(acc, a[0], b[0]);                 // substep 0

        CP_WAIT(STAGES - 2);                        // stage k+1 landed
        __syncthreads();

        if (k + 1 < KITERS)                         // prefetch next stage substep 0
            frag_load(a[0], b[0], sbase + ((k + 1) & (STAGES - 1)) * STAGE_BYTES,
                      aoff0, boff0);

        mma_block(acc, a[1], b[1]);                 // substep 1
    }

    // Epilogue: direct store + bias
    #pragma unroll
    for (int mi = 0; mi < 4; mi++) {
        int r = mbase + wm + mi * 16 + g;
        #pragma unroll
        for (int ni = 0; ni < 8; ni++) {
            int col = nbase + wn + ni * 8 + tig * 2;
            float2 bv = *(const float2*)(bias + col);
            float2 v0 = make_float2(acc[mi][ni][0] + bv.x, acc[mi][ni][1] + bv.y);
            float2 v1 = make_float2(acc[mi][ni][2] + bv.x, acc[mi][ni][3] + bv.y);
            *(float2*)(out + (size_t)r * OUT_F + col)       = v0;
            *(float2*)(out + (size_t)(r + 8) * OUT_F + col) = v1;
        }
    }
}

// ---------------------------------------------------------------------------
// Launch
// ---------------------------------------------------------------------------
extern "C" void kernel_launch(void* const* d_in, const int* in_sizes, int n_in,
                              void* d_out, int out_size)
{
    const float* x         = (const float*)d_in[0];
    const float* oft_r     = (const float*)d_in[1];
    const int*   codes     = (const int*)d_in[2];
    const float* codebooks = (const float*)d_in[3];
    const float* scales    = (const float*)d_in[4];
    const float* bias      = (const float*)d_in[5];
    float*       out       = (float*)d_out;

    cayley_kernel<<<NBLKS, dim3(32, 32)>>>(oft_r);
    prep_kernel<<<XBLKS + NBLKS * (OUT_F / 8), 256>>>(x, codes, codebooks, scales);

    int smem_bytes = STAGES * STAGE_BYTES;   // 96 KB
    cudaFuncSetAttribute(gemm_kernel, cudaFuncAttributeMaxDynamicSharedMemorySize, smem_bytes);
    gemm_kernel<<<dim3(OUT_F / TN, MROWS / TM), 256, smem_bytes>>>(bias, out);
}